// round 17
// baseline (speedup 1.0000x reference)
#include <cuda_runtime.h>

// newPad2d: replicate (edge) pad, width 2 on H and W.
// in:  (32, 256, 56, 56) fp32 = 98 MB  -> 8192 planes of 56x56
// out: (32, 256, 60, 60) fp32 = 112.5 MB -> 8192 planes of 60x60
//
// R16 probe — INVERTED cache residency. Working set (210.5 MB) > L2
// (126 MB), so only one side can be resident. Champion keeps the INPUT
// resident (~50 MB read misses) and drains all 112.5 MB of writes to
// DRAM each graph replay (~163 MB traffic). This variant tries keeping
// the OUTPUT resident instead (112.5 MB < 126 MB; dirty lines re-dirtied
// each replay -> writebacks mostly elided):
//   - stores: plain st.global.v4.b64 (write-allocate, evict-normal)
//   - loads:  createpolicy evict_first + ld.global.nc.L2::cache_hint
//             (stream input through without evicting output)
// If honored: traffic -> ~110-130 MB, ncu ~22-26 us. If hints inert
// (as in R6's opposite-direction test): neutral, champion stands.
//
// Body identical to champion: 2 vec8/thread, each half-vec4 row-local
// with w0 % 4 == 0 -> two 8B-aligned LDG.64 + 2 selects; 2 STG.256.
// nvec8 = 3,686,400 = 7200 blocks * 512 exactly.

#define IN_H   56
#define IN_W   56
#define PAD    2
#define PLANE_IN      (IN_H * IN_W)          // 3136
#define VEC_PER_ROW   15                     // vec4 per output row
#define VEC_PER_PLANE (60 * VEC_PER_ROW)     // 900 vec4 per plane
#define ILP 2                                // vec8 per thread
#define THREADS 256
#define CHUNK (THREADS * ILP)                // 512 vec8 per block

typedef unsigned long long ull;

__device__ __forceinline__ ull pack2(float lo, float hi) {
    return ((ull)__float_as_uint(hi) << 32) | (ull)__float_as_uint(lo);
}

// Plain (write-allocate, evict-normal) 256-bit store: let output live in L2.
__device__ __forceinline__ void stg256(void* p, float4 lo, float4 hi) {
    ull u0 = pack2(lo.x, lo.y);
    ull u1 = pack2(lo.z, lo.w);
    ull u2 = pack2(hi.x, hi.y);
    ull u3 = pack2(hi.z, hi.w);
    asm volatile("st.global.v4.b64 [%0], {%1,%2,%3,%4};"
                 :: "l"(p), "l"(u0), "l"(u1), "l"(u2), "l"(u3)
                 : "memory");
}

__device__ __forceinline__ unsigned long long mk_evict_first_policy() {
    unsigned long long pol;
    asm("createpolicy.fractional.L2::evict_first.b64 %0, 1.0;" : "=l"(pol));
    return pol;
}

// Streaming input load: evict_first so input doesn't displace output lines.
__device__ __forceinline__ float2 ldg_stream(const float* p, unsigned long long pol) {
    float2 v;
    asm("ld.global.nc.L2::cache_hint.v2.f32 {%0,%1}, [%2], %3;"
        : "=f"(v.x), "=f"(v.y) : "l"(p), "l"(pol));
    return v;
}

// Compute one output vec4. v4idx = global vec4 index.
__device__ __forceinline__ float4 make_vec4(const float* __restrict__ x, int v4idx,
                                            unsigned long long pol)
{
    int plane = v4idx / VEC_PER_PLANE;
    int rem   = v4idx - plane * VEC_PER_PLANE;
    int h     = rem / VEC_PER_ROW;
    int w     = (rem - h * VEC_PER_ROW) * 4;
    int hin   = min(max(h - PAD, 0), IN_H - 1);
    int off   = plane * PLANE_IN + hin * IN_W;   // max ~25.7M, fits 32-bit

    // both addresses 8-byte aligned
    float2 a = ldg_stream(x + off + max(w - 2, 0), pol);
    float2 b = ldg_stream(x + off + min(w, IN_W - 2), pol);

    float4 v;
    v.x = a.x;
    v.y = (w == 0)    ? a.x : a.y;   // left edge replicates col 0
    v.z = (w == IN_W) ? b.y : b.x;   // right edge replicates col 55
    v.w = b.y;
    return v;
}

__global__ __launch_bounds__(THREADS)
void pad2d_edge_v8_inv(const float* __restrict__ x,
                       float* __restrict__ out)
{
    const int base8 = blockIdx.x * CHUNK + threadIdx.x;   // vec8 index
    const unsigned long long pol = mk_evict_first_policy();

    float4 lo[ILP], hi[ILP];
#pragma unroll
    for (int k = 0; k < ILP; k++) {
        int v8 = base8 + k * THREADS;
        lo[k] = make_vec4(x, 2 * v8, pol);
        hi[k] = make_vec4(x, 2 * v8 + 1, pol);
    }

#pragma unroll
    for (int k = 0; k < ILP; k++) {
        int v8 = base8 + k * THREADS;
        stg256(out + (size_t)v8 * 8, lo[k], hi[k]);
    }
}

extern "C" void kernel_launch(void* const* d_in, const int* in_sizes, int n_in,
                              void* d_out, int out_size)
{
    const float* x = (const float*)d_in[0];
    float* out = (float*)d_out;

    int nvec8 = out_size / 8;        // 3,686,400
    int blocks = nvec8 / CHUNK;      // 7200 exactly
    pad2d_edge_v8_inv<<<blocks, THREADS>>>(x, out);
}